// round 8
// baseline (speedup 1.0000x reference)
#include <cuda_runtime.h>
#include <cstdint>

// Problem constants (from reference setup_inputs)
#define BB 16
#define TT 4096
#define DD 768
#define SS 64
#define D4 (DD / 4)          // 192 float4 lanes per row
#define OUT_VEC ((size_t)BB * 2 * SS * DD)   // 1,572,864 floats

__device__ __forceinline__ uint32_t smem_u32(const void* p) {
    uint32_t a;
    asm("{ .reg .u64 t; cvta.to.shared.u64 t, %1; cvt.u32.u64 %0, t; }"
        : "=r"(a) : "l"(p));
    return a;
}

// Cluster of 2 CTAs per (b, s) segment: rank 0 takes the first half of the
// token span, rank 1 the second half. Rank 1 ships its 8 partials/thread to
// rank 0 via DSMEM; rank 0 combines, applies masks/empty-fallback, writes out.
// Doubles resident warps (196K -> 392K threads) at zero extra DRAM traffic.
__global__ __launch_bounds__(192, 9) __cluster_dims__(2, 1, 1)
void pooling_kernel(
    const float* __restrict__ wv,           // [B, T, D]
    const int* __restrict__ rep_ids,        // [B, S]
    const int* __restrict__ rep_mask,       // [B, S] bool marshaled as int32
    const int* __restrict__ lens,           // [B, S]
    const int* __restrict__ len_mask,       // [B, S] bool marshaled as int32
    float* __restrict__ out,                // [B, 2S, D] (+ optional [B, 2S] mask tail)
    int write_mask_tail)
{
    const int seg  = blockIdx.x >> 1;       // b*S + s
    const int rank = blockIdx.x & 1;        // cluster rank (cluster dim x = 2)
    const int b = seg / SS;
    const int s = seg % SS;
    const int tid = threadIdx.x;            // 0..191
    const int lane = tid & 31;
    const int wid = tid >> 5;

    __shared__ int sh_bounds[2];
    __shared__ float sh_xfer[192 * 8];      // rank1 -> rank0 partials
    __shared__ float sh_warp[6];

    if (tid == 0) {
        const int* lrow = lens + b * SS;
        int start = 0;
        #pragma unroll 8
        for (int i = 0; i < SS; i++) {
            int li = lrow[i];
            if (i < s) start += li;
        }
        long long endl = (long long)start + (long long)lrow[s];
        if (start < 0) start = 0;
        if (start > TT) start = TT;
        int end = (endl > TT) ? TT : (int)endl;
        if (end < start) end = start;
        sh_bounds[0] = start;
        sh_bounds[1] = end;
    }
    __syncthreads();
    const int start = sh_bounds[0];
    const int end   = sh_bounds[1];
    const int len   = end - start;
    const int mid   = start + ((len + 1) >> 1);
    const int t0    = rank ? mid : start;
    const int t1    = rank ? end : mid;

    const float4* base = reinterpret_cast<const float4*>(wv + (size_t)b * TT * DD);

    // Rank 0 also owns the rep gather + masks (its token range contains rid here).
    float4 r = make_float4(0.f, 0.f, 0.f, 0.f);
    float rm = 0.f, lm = 0.f;
    if (rank == 0) {
        int rid = rep_ids[b * SS + s];
        if (rid < 0) rid = 0;
        if (rid >= TT) rid = TT - 1;
        r = __ldg(base + (size_t)rid * D4 + tid);
        rm = (rep_mask[b * SS + s] != 0) ? 1.f : 0.f;
        lm = (len_mask[b * SS + s] != 0) ? 1.f : 0.f;
    }

    const float4* p = base + (size_t)t0 * D4 + tid;

    float sx = 0.f, sy = 0.f, sz = 0.f, sw = 0.f;
    float cx = 0.f, cy = 0.f, cz = 0.f, cw = 0.f;

    int t = t0;
    // Main loop: 4 tokens per iteration (divides half-span 32 exactly).
    for (; t + 4 <= t1; t += 4, p += 4 * D4) {
        float4 v0 = __ldcs(p);
        float4 v1 = __ldcs(p + D4);
        float4 v2 = __ldcs(p + 2 * D4);
        float4 v3 = __ldcs(p + 3 * D4);

        sx += v0.x + v1.x + v2.x + v3.x;
        sy += v0.y + v1.y + v2.y + v3.y;
        sz += v0.z + v1.z + v2.z + v3.z;
        sw += v0.w + v1.w + v2.w + v3.w;

        cx += ((v0.x != 0.f) ? 1.f : 0.f) + ((v1.x != 0.f) ? 1.f : 0.f)
            + ((v2.x != 0.f) ? 1.f : 0.f) + ((v3.x != 0.f) ? 1.f : 0.f);
        cy += ((v0.y != 0.f) ? 1.f : 0.f) + ((v1.y != 0.f) ? 1.f : 0.f)
            + ((v2.y != 0.f) ? 1.f : 0.f) + ((v3.y != 0.f) ? 1.f : 0.f);
        cz += ((v0.z != 0.f) ? 1.f : 0.f) + ((v1.z != 0.f) ? 1.f : 0.f)
            + ((v2.z != 0.f) ? 1.f : 0.f) + ((v3.z != 0.f) ? 1.f : 0.f);
        cw += ((v0.w != 0.f) ? 1.f : 0.f) + ((v1.w != 0.f) ? 1.f : 0.f)
            + ((v2.w != 0.f) ? 1.f : 0.f) + ((v3.w != 0.f) ? 1.f : 0.f);
    }
    // Tail (general correctness for odd spans)
    for (; t < t1; t++, p += D4) {
        float4 v = __ldcs(p);
        sx += v.x; sy += v.y; sz += v.z; sw += v.w;
        cx += (v.x != 0.f) ? 1.f : 0.f;
        cy += (v.y != 0.f) ? 1.f : 0.f;
        cz += (v.z != 0.f) ? 1.f : 0.f;
        cw += (v.w != 0.f) ? 1.f : 0.f;
    }

    // Rank 1 pushes partials into rank 0's sh_xfer via DSMEM.
    if (rank == 1) {
        uint32_t laddr = smem_u32(&sh_xfer[tid * 8]);
        uint32_t raddr;
        asm volatile("mapa.shared::cluster.u32 %0, %1, %2;"
                     : "=r"(raddr) : "r"(laddr), "r"(0));
        asm volatile("st.shared::cluster.f32 [%0+ 0], %1;" :: "r"(raddr), "f"(sx) : "memory");
        asm volatile("st.shared::cluster.f32 [%0+ 4], %1;" :: "r"(raddr), "f"(sy) : "memory");
        asm volatile("st.shared::cluster.f32 [%0+ 8], %1;" :: "r"(raddr), "f"(sz) : "memory");
        asm volatile("st.shared::cluster.f32 [%0+12], %1;" :: "r"(raddr), "f"(sw) : "memory");
        asm volatile("st.shared::cluster.f32 [%0+16], %1;" :: "r"(raddr), "f"(cx) : "memory");
        asm volatile("st.shared::cluster.f32 [%0+20], %1;" :: "r"(raddr), "f"(cy) : "memory");
        asm volatile("st.shared::cluster.f32 [%0+24], %1;" :: "r"(raddr), "f"(cz) : "memory");
        asm volatile("st.shared::cluster.f32 [%0+28], %1;" :: "r"(raddr), "f"(cw) : "memory");
    }
    // Release/acquire cluster barrier: rank1's DSMEM stores -> visible to rank0.
    asm volatile("barrier.cluster.arrive.aligned;" ::: "memory");
    asm volatile("barrier.cluster.wait.aligned;" ::: "memory");
    if (rank == 1) return;

    // Combine halves (thread t reads slot t: one-to-one, no block sync needed).
    sx += sh_xfer[tid * 8 + 0]; sy += sh_xfer[tid * 8 + 1];
    sz += sh_xfer[tid * 8 + 2]; sw += sh_xfer[tid * 8 + 3];
    cx += sh_xfer[tid * 8 + 4]; cy += sh_xfer[tid * 8 + 5];
    cz += sh_xfer[tid * 8 + 6]; cw += sh_xfer[tid * 8 + 7];

    // Whole-segment emptiness check (seg_cnt.sum(-1) == 0), warp-shuffle reduce.
    float tot = cx + cy + cz + cw;
    #pragma unroll
    for (int off = 16; off > 0; off >>= 1)
        tot += __shfl_xor_sync(0xffffffffu, tot, off);
    if (lane == 0) sh_warp[wid] = tot;
    __syncthreads();
    float block_tot = sh_warp[0] + sh_warp[1] + sh_warp[2]
                    + sh_warp[3] + sh_warp[4] + sh_warp[5];
    const bool empty = (block_tot == 0.f);

    float4 o;
    if (empty) {
        // fallback to word_vectors[0, 0, :]
        float4 w0 = __ldg(reinterpret_cast<const float4*>(wv) + tid);
        o.x = w0.x * lm; o.y = w0.y * lm; o.z = w0.z * lm; o.w = w0.w * lm;
    } else {
        float dx = (cx == 0.f) ? 1.f : cx;
        float dy = (cy == 0.f) ? 1.f : cy;
        float dz = (cz == 0.f) ? 1.f : cz;
        float dw = (cw == 0.f) ? 1.f : cw;
        o.x = (sx / dx) * lm;
        o.y = (sy / dy) * lm;
        o.z = (sz / dz) * lm;
        o.w = (sw / dw) * lm;
    }
    float4* out4 = reinterpret_cast<float4*>(out);
    // mean_vec -> out[b, S + s, :]
    __stcs(&out4[((size_t)b * 2 * SS + SS + s) * D4 + tid], o);
    // rep_vec -> out[b, s, :]
    r.x *= rm; r.y *= rm; r.z *= rm; r.w *= rm;
    __stcs(&out4[((size_t)b * 2 * SS + s) * D4 + tid], r);

    // output mask tail (flattened tuple): out_tail[b, c] with c in [0, 2S)
    if (write_mask_tail) {
        float* out_tail = out + OUT_VEC;
        if (tid == 0) out_tail[b * 2 * SS + s]      = rm;   // rep mask half
        if (tid == 1) out_tail[b * 2 * SS + SS + s] = lm;   // len mask half
    }
}

extern "C" void kernel_launch(void* const* d_in, const int* in_sizes, int n_in,
                              void* d_out, int out_size)
{
    const float* wv       = (const float*)d_in[0];
    const int*   rep_ids  = (const int*)d_in[1];
    const int*   rep_mask = (const int*)d_in[2];
    const int*   lens     = (const int*)d_in[3];
    const int*   len_mask = (const int*)d_in[4];
    float* out = (float*)d_out;

    int write_mask_tail = ((size_t)out_size > OUT_VEC) ? 1 : 0;
    pooling_kernel<<<BB * SS * 2, 192>>>(wv, rep_ids, rep_mask, lens, len_mask, out,
                                         write_mask_tail);
}

// round 9
// speedup vs baseline: 1.4214x; 1.4214x over previous
#include <cuda_runtime.h>
#include <cstdint>

// Problem constants (from reference setup_inputs)
#define BB 16
#define TT 4096
#define DD 768
#define SS 64
#define D4 (DD / 4)          // 192 float4 lanes per row
#define OUT_VEC ((size_t)BB * 2 * SS * DD)   // 1,572,864 floats

#define CHUNK 4                          // tokens per bulk-copy chunk
#define STAGE_FLOATS (CHUNK * DD)        // 3072 floats = 12288 bytes
#define NSTAGE 2

__device__ __forceinline__ uint32_t smem_u32(const void* p) {
    uint32_t a;
    asm("{ .reg .u64 t; cvta.to.shared.u64 t, %1; cvt.u32.u64 %0, t; }"
        : "=r"(a) : "l"(p));
    return a;
}

__device__ __forceinline__ void mbar_wait(uint32_t mbar, uint32_t parity) {
    uint32_t done;
    asm volatile(
        "{\n\t.reg .pred p;\n\t"
        "mbarrier.try_wait.parity.acquire.cta.shared::cta.b64 p, [%1], %2;\n\t"
        "selp.b32 %0, 1, 0, p;\n\t}"
        : "=r"(done) : "r"(mbar), "r"(parity) : "memory");
    while (!done) {
        asm volatile(
            "{\n\t.reg .pred p;\n\t"
            "mbarrier.try_wait.parity.acquire.cta.shared::cta.b64 p, [%1], %2, 0x989680;\n\t"
            "selp.b32 %0, 1, 0, p;\n\t}"
            : "=r"(done) : "r"(mbar), "r"(parity) : "memory");
    }
}

// One block per (b, s) segment. 2-stage cp.async.bulk pipeline streams the
// segment's token rows into smem (12 KB chunks); 192 threads reduce from smem.
// Outstanding HBM bytes come from the bulk-copy engine, not warp LDG slots.
__global__ __launch_bounds__(192, 8) void pooling_kernel(
    const float* __restrict__ wv,           // [B, T, D]
    const int* __restrict__ rep_ids,        // [B, S]
    const int* __restrict__ rep_mask,       // [B, S] bool marshaled as int32
    const int* __restrict__ lens,           // [B, S]
    const int* __restrict__ len_mask,       // [B, S] bool marshaled as int32
    float* __restrict__ out,                // [B, 2S, D] (+ optional [B, 2S] mask tail)
    int write_mask_tail)
{
    __shared__ __align__(128) float buf[NSTAGE][STAGE_FLOATS];
    __shared__ __align__(8) unsigned long long mbar[NSTAGE];
    __shared__ int sh_bounds[2];
    __shared__ float sh_warp[6];

    const int blk = blockIdx.x;             // b*S + s
    const int b = blk / SS;
    const int s = blk % SS;
    const int tid = threadIdx.x;            // 0..191
    const int lane = tid & 31;
    const int wid = tid >> 5;

    if (tid == 0) {
        const int* lrow = lens + b * SS;
        int start = 0;
        #pragma unroll 8
        for (int i = 0; i < SS; i++) {
            int li = lrow[i];
            if (i < s) start += li;
        }
        long long endl = (long long)start + (long long)lrow[s];
        if (start < 0) start = 0;
        if (start > TT) start = TT;
        int end = (endl > TT) ? TT : (int)endl;
        if (end < start) end = start;
        sh_bounds[0] = start;
        sh_bounds[1] = end;
        // init mbarriers (single arriver: the expect_tx arrive)
        uint32_t b0 = smem_u32(&mbar[0]);
        uint32_t b1 = smem_u32(&mbar[1]);
        asm volatile("mbarrier.init.shared.b64 [%0], 1;" :: "r"(b0) : "memory");
        asm volatile("mbarrier.init.shared.b64 [%0], 1;" :: "r"(b1) : "memory");
        asm volatile("fence.proxy.async.shared::cta;" ::: "memory");
    }
    __syncthreads();
    const int start = sh_bounds[0];
    const int end   = sh_bounds[1];
    const int len   = end - start;
    const int nchunks = (len + CHUNK - 1) / CHUNK;

    const float4* base = reinterpret_cast<const float4*>(wv + (size_t)b * TT * DD);
    const char* src_base = reinterpret_cast<const char*>(wv + (size_t)b * TT * DD
                                                            + (size_t)start * DD);

    // Producer: issue chunk i into stage i&1 (tid 0 only).
    auto issue = [&](int i) {
        int t0 = i * CHUNK;
        int rows = len - t0;
        if (rows > CHUNK) rows = CHUNK;
        uint32_t bytes = (uint32_t)rows * DD * 4u;
        uint32_t dst = smem_u32(&buf[i & 1][0]);
        uint32_t bar = smem_u32(&mbar[i & 1]);
        asm volatile("mbarrier.arrive.expect_tx.shared.b64 _, [%0], %1;"
                     :: "r"(bar), "r"(bytes) : "memory");
        asm volatile(
            "cp.async.bulk.shared::cluster.global.mbarrier::complete_tx::bytes "
            "[%0], [%1], %2, [%3];"
            :: "r"(dst), "l"(src_base + (size_t)t0 * DD * 4), "r"(bytes), "r"(bar)
            : "memory");
    };
    if (tid == 0) {
        if (nchunks > 0) issue(0);
        if (nchunks > 1) issue(1);
    }

    // Rep gather overlaps with the pipeline (its row is inside this span here).
    int rid = rep_ids[b * SS + s];
    if (rid < 0) rid = 0;
    if (rid >= TT) rid = TT - 1;
    float4 r = __ldg(base + (size_t)rid * D4 + tid);

    float sx = 0.f, sy = 0.f, sz = 0.f, sw = 0.f;
    float cx = 0.f, cy = 0.f, cz = 0.f, cw = 0.f;

    for (int i = 0; i < nchunks; i++) {
        const int stage = i & 1;
        const uint32_t parity = (uint32_t)((i >> 1) & 1);
        mbar_wait(smem_u32(&mbar[stage]), parity);

        int rows = len - i * CHUNK;
        if (rows > CHUNK) rows = CHUNK;
        const float4* bp = reinterpret_cast<const float4*>(&buf[stage][0]);
        #pragma unroll
        for (int rr = 0; rr < CHUNK; rr++) {
            if (rr < rows) {
                float4 v = bp[rr * D4 + tid];
                sx += v.x; sy += v.y; sz += v.z; sw += v.w;
                cx += (v.x != 0.f) ? 1.f : 0.f;
                cy += (v.y != 0.f) ? 1.f : 0.f;
                cz += (v.z != 0.f) ? 1.f : 0.f;
                cw += (v.w != 0.f) ? 1.f : 0.f;
            }
        }
        __syncthreads();   // all threads done reading this stage
        if (tid == 0 && i + 2 < nchunks) issue(i + 2);
    }

    // Whole-segment emptiness check (seg_cnt.sum(-1) == 0), warp-shuffle reduce.
    float tot = cx + cy + cz + cw;
    #pragma unroll
    for (int off = 16; off > 0; off >>= 1)
        tot += __shfl_xor_sync(0xffffffffu, tot, off);
    if (lane == 0) sh_warp[wid] = tot;
    __syncthreads();
    float block_tot = sh_warp[0] + sh_warp[1] + sh_warp[2]
                    + sh_warp[3] + sh_warp[4] + sh_warp[5];
    const bool empty = (block_tot == 0.f);

    const float lm = (len_mask[b * SS + s] != 0) ? 1.f : 0.f;
    const float rm = (rep_mask[b * SS + s] != 0) ? 1.f : 0.f;

    float4 o;
    if (empty) {
        // fallback to word_vectors[0, 0, :]
        float4 w0 = __ldg(reinterpret_cast<const float4*>(wv) + tid);
        o.x = w0.x * lm; o.y = w0.y * lm; o.z = w0.z * lm; o.w = w0.w * lm;
    } else {
        float dx = (cx == 0.f) ? 1.f : cx;
        float dy = (cy == 0.f) ? 1.f : cy;
        float dz = (cz == 0.f) ? 1.f : cz;
        float dw = (cw == 0.f) ? 1.f : cw;
        o.x = (sx / dx) * lm;
        o.y = (sy / dy) * lm;
        o.z = (sz / dz) * lm;
        o.w = (sw / dw) * lm;
    }
    float4* out4 = reinterpret_cast<float4*>(out);
    // mean_vec -> out[b, S + s, :]
    __stcs(&out4[((size_t)b * 2 * SS + SS + s) * D4 + tid], o);
    // rep_vec -> out[b, s, :]
    r.x *= rm; r.y *= rm; r.z *= rm; r.w *= rm;
    __stcs(&out4[((size_t)b * 2 * SS + s) * D4 + tid], r);

    // output mask tail (flattened tuple): out_tail[b, c] with c in [0, 2S)
    if (write_mask_tail) {
        float* out_tail = out + OUT_VEC;
        if (tid == 0) out_tail[b * 2 * SS + s]      = rm;   // rep mask half
        if (tid == 1) out_tail[b * 2 * SS + SS + s] = lm;   // len mask half
    }
}

extern "C" void kernel_launch(void* const* d_in, const int* in_sizes, int n_in,
                              void* d_out, int out_size)
{
    const float* wv       = (const float*)d_in[0];
    const int*   rep_ids  = (const int*)d_in[1];
    const int*   rep_mask = (const int*)d_in[2];
    const int*   lens     = (const int*)d_in[3];
    const int*   len_mask = (const int*)d_in[4];
    float* out = (float*)d_out;

    int write_mask_tail = ((size_t)out_size > OUT_VEC) ? 1 : 0;
    pooling_kernel<<<BB * SS, 192>>>(wv, rep_ids, rep_mask, lens, len_mask, out,
                                     write_mask_tail);
}

// round 10
// speedup vs baseline: 1.4919x; 1.0496x over previous
#include <cuda_runtime.h>
#include <cstdint>

// Problem constants (from reference setup_inputs)
#define BB 16
#define TT 4096
#define DD 768
#define SS 64
#define D4 (DD / 4)          // 192 float4 lanes per row
#define OUT_VEC ((size_t)BB * 2 * SS * DD)   // 1,572,864 floats

#define CHUNK 4                          // tokens per bulk-copy chunk
#define STAGE_FLOATS (CHUNK * DD)        // 3072 floats = 12288 bytes
#define NSTAGE 2

__device__ __forceinline__ uint32_t smem_u32(const void* p) {
    uint32_t a;
    asm("{ .reg .u64 t; cvta.to.shared.u64 t, %1; cvt.u32.u64 %0, t; }"
        : "=r"(a) : "l"(p));
    return a;
}

__device__ __forceinline__ void mbar_wait(uint32_t mbar, uint32_t parity) {
    uint32_t done;
    asm volatile(
        "{\n\t.reg .pred p;\n\t"
        "mbarrier.try_wait.parity.acquire.cta.shared::cta.b64 p, [%1], %2;\n\t"
        "selp.b32 %0, 1, 0, p;\n\t}"
        : "=r"(done) : "r"(mbar), "r"(parity) : "memory");
    while (!done) {
        asm volatile(
            "{\n\t.reg .pred p;\n\t"
            "mbarrier.try_wait.parity.acquire.cta.shared::cta.b64 p, [%1], %2, 0x989680;\n\t"
            "selp.b32 %0, 1, 0, p;\n\t}"
            : "=r"(done) : "r"(mbar), "r"(parity) : "memory");
    }
}

// One block per (b, s) segment. 2-stage cp.async.bulk pipeline streams the
// segment's token rows into smem (12 KB chunks); 192 threads reduce from smem.
// The rep-vector row is extracted from the smem stream when it lies in-span
// (saves a duplicate DRAM gather); LDG fallback otherwise.
__global__ __launch_bounds__(192, 8) void pooling_kernel(
    const float* __restrict__ wv,           // [B, T, D]
    const int* __restrict__ rep_ids,        // [B, S]
    const int* __restrict__ rep_mask,       // [B, S] bool marshaled as int32
    const int* __restrict__ lens,           // [B, S]
    const int* __restrict__ len_mask,       // [B, S] bool marshaled as int32
    float* __restrict__ out,                // [B, 2S, D] (+ optional [B, 2S] mask tail)
    int write_mask_tail)
{
    __shared__ __align__(128) float buf[NSTAGE][STAGE_FLOATS];
    __shared__ __align__(8) unsigned long long mbar[NSTAGE];
    __shared__ int sh_bounds[2];
    __shared__ float sh_warp[6];

    const int blk = blockIdx.x;             // b*S + s
    const int b = blk / SS;
    const int s = blk % SS;
    const int tid = threadIdx.x;            // 0..191
    const int lane = tid & 31;
    const int wid = tid >> 5;

    if (tid == 0) {
        const int* lrow = lens + b * SS;
        int start = 0;
        #pragma unroll 8
        for (int i = 0; i < SS; i++) {
            int li = lrow[i];
            if (i < s) start += li;
        }
        long long endl = (long long)start + (long long)lrow[s];
        if (start < 0) start = 0;
        if (start > TT) start = TT;
        int end = (endl > TT) ? TT : (int)endl;
        if (end < start) end = start;
        sh_bounds[0] = start;
        sh_bounds[1] = end;
        uint32_t b0 = smem_u32(&mbar[0]);
        uint32_t b1 = smem_u32(&mbar[1]);
        asm volatile("mbarrier.init.shared.b64 [%0], 1;" :: "r"(b0) : "memory");
        asm volatile("mbarrier.init.shared.b64 [%0], 1;" :: "r"(b1) : "memory");
        asm volatile("fence.proxy.async.shared::cta;" ::: "memory");
    }
    __syncthreads();
    const int start = sh_bounds[0];
    const int end   = sh_bounds[1];
    const int len   = end - start;
    const int nchunks = (len + CHUNK - 1) / CHUNK;

    const float4* base = reinterpret_cast<const float4*>(wv + (size_t)b * TT * DD);
    const char* src_base = reinterpret_cast<const char*>(wv + (size_t)b * TT * DD
                                                            + (size_t)start * DD);

    auto issue = [&](int i) {
        int t0 = i * CHUNK;
        int rows = len - t0;
        if (rows > CHUNK) rows = CHUNK;
        uint32_t bytes = (uint32_t)rows * DD * 4u;
        uint32_t dst = smem_u32(&buf[i & 1][0]);
        uint32_t bar = smem_u32(&mbar[i & 1]);
        asm volatile("mbarrier.arrive.expect_tx.shared.b64 _, [%0], %1;"
                     :: "r"(bar), "r"(bytes) : "memory");
        asm volatile(
            "cp.async.bulk.shared::cluster.global.mbarrier::complete_tx::bytes "
            "[%0], [%1], %2, [%3];"
            :: "r"(dst), "l"(src_base + (size_t)t0 * DD * 4), "r"(bytes), "r"(bar)
            : "memory");
    };
    if (tid == 0) {
        if (nchunks > 0) issue(0);
        if (nchunks > 1) issue(1);
    }

    // Masks early (tiny, overlaps pipeline fill).
    const float lm = (len_mask[b * SS + s] != 0) ? 1.f : 0.f;
    const float rm = (rep_mask[b * SS + s] != 0) ? 1.f : 0.f;

    // Rep row: in-span -> grab from smem stream (no extra DRAM traffic);
    // out-of-span -> LDG fallback.
    int rid = rep_ids[b * SS + s];
    if (rid < 0) rid = 0;
    if (rid >= TT) rid = TT - 1;
    const bool rep_in_span = (rid >= start) && (rid < end);
    const int rep_chunk = rep_in_span ? (rid - start) / CHUNK : -1;
    const int rep_row   = rep_in_span ? (rid - start) % CHUNK : 0;
    float4 r;
    if (!rep_in_span) {
        r = __ldg(base + (size_t)rid * D4 + tid);
    } else {
        r = make_float4(0.f, 0.f, 0.f, 0.f);
    }

    float sx = 0.f, sy = 0.f, sz = 0.f, sw = 0.f;
    float cx = 0.f, cy = 0.f, cz = 0.f, cw = 0.f;

    for (int i = 0; i < nchunks; i++) {
        const int stage = i & 1;
        const uint32_t parity = (uint32_t)((i >> 1) & 1);
        mbar_wait(smem_u32(&mbar[stage]), parity);

        const float4* bp = reinterpret_cast<const float4*>(&buf[stage][0]);
        if (i == rep_chunk) {
            r = bp[rep_row * D4 + tid];
        }

        int rows = len - i * CHUNK;
        if (rows > CHUNK) rows = CHUNK;
        #pragma unroll
        for (int rr = 0; rr < CHUNK; rr++) {
            if (rr < rows) {
                float4 v = bp[rr * D4 + tid];
                sx += v.x; sy += v.y; sz += v.z; sw += v.w;
                cx += (v.x != 0.f) ? 1.f : 0.f;
                cy += (v.y != 0.f) ? 1.f : 0.f;
                cz += (v.z != 0.f) ? 1.f : 0.f;
                cw += (v.w != 0.f) ? 1.f : 0.f;
            }
        }
        __syncthreads();   // all threads done reading this stage
        if (tid == 0 && i + 2 < nchunks) issue(i + 2);
    }

    // Whole-segment emptiness check (seg_cnt.sum(-1) == 0), warp-shuffle reduce.
    float tot = cx + cy + cz + cw;
    #pragma unroll
    for (int off = 16; off > 0; off >>= 1)
        tot += __shfl_xor_sync(0xffffffffu, tot, off);
    if (lane == 0) sh_warp[wid] = tot;
    __syncthreads();
    float block_tot = sh_warp[0] + sh_warp[1] + sh_warp[2]
                    + sh_warp[3] + sh_warp[4] + sh_warp[5];
    const bool empty = (block_tot == 0.f);

    float4 o;
    if (empty) {
        // fallback to word_vectors[0, 0, :]
        float4 w0 = __ldg(reinterpret_cast<const float4*>(wv) + tid);
        o.x = w0.x * lm; o.y = w0.y * lm; o.z = w0.z * lm; o.w = w0.w * lm;
    } else {
        float dx = (cx == 0.f) ? 1.f : cx;
        float dy = (cy == 0.f) ? 1.f : cy;
        float dz = (cz == 0.f) ? 1.f : cz;
        float dw = (cw == 0.f) ? 1.f : cw;
        o.x = (sx / dx) * lm;
        o.y = (sy / dy) * lm;
        o.z = (sz / dz) * lm;
        o.w = (sw / dw) * lm;
    }
    float4* out4 = reinterpret_cast<float4*>(out);
    // mean_vec -> out[b, S + s, :]
    __stcs(&out4[((size_t)b * 2 * SS + SS + s) * D4 + tid], o);
    // rep_vec -> out[b, s, :]
    r.x *= rm; r.y *= rm; r.z *= rm; r.w *= rm;
    __stcs(&out4[((size_t)b * 2 * SS + s) * D4 + tid], r);

    // output mask tail (flattened tuple): out_tail[b, c] with c in [0, 2S)
    if (write_mask_tail) {
        float* out_tail = out + OUT_VEC;
        if (tid == 0) out_tail[b * 2 * SS + s]      = rm;   // rep mask half
        if (tid == 1) out_tail[b * 2 * SS + SS + s] = lm;   // len mask half
    }
}

extern "C" void kernel_launch(void* const* d_in, const int* in_sizes, int n_in,
                              void* d_out, int out_size)
{
    const float* wv       = (const float*)d_in[0];
    const int*   rep_ids  = (const int*)d_in[1];
    const int*   rep_mask = (const int*)d_in[2];
    const int*   lens     = (const int*)d_in[3];
    const int*   len_mask = (const int*)d_in[4];
    float* out = (float*)d_out;

    int write_mask_tail = ((size_t)out_size > OUT_VEC) ? 1 : 0;
    pooling_kernel<<<BB * SS, 192>>>(wv, rep_ids, rep_mask, lens, len_mask, out,
                                     write_mask_tail);
}